// round 2
// baseline (speedup 1.0000x reference)
#include <cuda_runtime.h>
#include <cuda_bf16.h>
#include <cstdint>

#define N_NODES 50000
#define E0      800000
#define ETOT    850000   // E0 + N self loops
#define IN_F    256
#define HID     128
#define HEADS1  8
#define OUT_F   64

// ---------------- scratch (device globals; no allocation allowed) ----------------
__device__ __align__(16) float    g_h1  [N_NODES * HID];    // x@W1
__device__ __align__(16) float    g_out1[N_NODES * HID];    // layer1 aggregate
__device__ __align__(16) float    g_h2  [N_NODES * OUT_F];  // elu(out1+b1)@W2
__device__ __align__(16) float    g_out2[N_NODES * OUT_F];  // layer2 aggregate
__device__ float    g_as1[N_NODES * HEADS1];
__device__ float    g_ad1[N_NODES * HEADS1];
__device__ float    g_den1[N_NODES * HEADS1];
__device__ unsigned g_emax1[N_NODES * HEADS1];
__device__ float    g_as2[N_NODES];
__device__ float    g_ad2[N_NODES];
__device__ float    g_den2[N_NODES];
__device__ unsigned g_emax2[N_NODES];

// ---------------- helpers ----------------
__device__ __forceinline__ unsigned fenc(float f) {
    unsigned u = __float_as_uint(f);
    return (u & 0x80000000u) ? ~u : (u | 0x80000000u);
}
__device__ __forceinline__ float fdec(unsigned u) {
    return (u & 0x80000000u) ? __uint_as_float(u & 0x7fffffffu) : __uint_as_float(~u);
}
__device__ __forceinline__ float lrelu(float v) { return v > 0.f ? v : 0.2f * v; }
__device__ __forceinline__ float eluf(float v)  { return v > 0.f ? v : (__expf(v) - 1.f); }

// ---------------- init (zero accumulators) ----------------
__global__ void init_kernel() {
    int i = blockIdx.x * blockDim.x + threadIdx.x;
    float4 z = make_float4(0.f, 0.f, 0.f, 0.f);
    if (i < N_NODES * HID / 4)   ((float4*)g_out1)[i] = z;
    if (i < N_NODES * OUT_F / 4) ((float4*)g_out2)[i] = z;
    if (i < N_NODES * HEADS1) { g_den1[i] = 0.f; g_emax1[i] = 0u; }
    if (i < N_NODES)          { g_den2[i] = 0.f; g_emax2[i] = 0u; }
}

// ---------------- register-blocked GEMM: H = f(X) @ W ----------------
// BM=128 rows, BN=NOUT (128 or 64), BK=16, 256 threads, 8xRN micro-tile.
// SECOND: X = elu(g_out1 + b1) (fused on load), output -> g_h2; else X=Xin -> g_h1.
template<int KDIM, int NOUT, bool SECOND>
__global__ __launch_bounds__(256, 2)
void gemm_kernel(const float* __restrict__ Xin, const float* __restrict__ W,
                 const float* __restrict__ bvec)
{
    constexpr int BM = 128, BK = 16;
    constexpr int RN = (NOUT >= 128) ? 8 : 4;
    const float* X    = SECOND ? g_out1 : Xin;
    float*       Hout = SECOND ? g_h2   : g_h1;

    __shared__ float As[BK][BM];
    __shared__ float Bs[BK][NOUT];

    const int tid = threadIdx.x;
    const int tx = tid & 15, ty = tid >> 4;
    const int row0 = blockIdx.x * BM;

    float acc[8][RN];
#pragma unroll
    for (int i = 0; i < 8; i++)
#pragma unroll
        for (int j = 0; j < RN; j++) acc[i][j] = 0.f;

    for (int k0 = 0; k0 < KDIM; k0 += BK) {
        // load A tile (transposed into As[k][m])
#pragma unroll
        for (int rep = 0; rep < 2; rep++) {
            int m = (tid >> 2) + rep * 64;
            int kk4 = (tid & 3) << 2;
            float4 v = make_float4(0.f, 0.f, 0.f, 0.f);
            int r = row0 + m;
            if (r < N_NODES) v = *(const float4*)(X + (size_t)r * KDIM + k0 + kk4);
            if (SECOND) {
                v.x = eluf(v.x + bvec[k0 + kk4 + 0]);
                v.y = eluf(v.y + bvec[k0 + kk4 + 1]);
                v.z = eluf(v.z + bvec[k0 + kk4 + 2]);
                v.w = eluf(v.w + bvec[k0 + kk4 + 3]);
            }
            As[kk4 + 0][m] = v.x; As[kk4 + 1][m] = v.y;
            As[kk4 + 2][m] = v.z; As[kk4 + 3][m] = v.w;
        }
        // load B tile
#pragma unroll
        for (int i = 0; i < (BK * NOUT / 4) / 256; i++) {
            int idx = tid + i * 256;
            int kk = idx / (NOUT / 4), c4 = (idx % (NOUT / 4)) * 4;
            *(float4*)&Bs[kk][c4] = *(const float4*)(W + (size_t)(k0 + kk) * NOUT + c4);
        }
        __syncthreads();
#pragma unroll
        for (int kk = 0; kk < BK; kk++) {
            float a[8], b[RN];
            float4 a0 = *(const float4*)&As[kk][ty * 4];
            float4 a1 = *(const float4*)&As[kk][ty * 4 + 64];
            a[0]=a0.x; a[1]=a0.y; a[2]=a0.z; a[3]=a0.w;
            a[4]=a1.x; a[5]=a1.y; a[6]=a1.z; a[7]=a1.w;
            float4 b0 = *(const float4*)&Bs[kk][tx * 4];
            b[0]=b0.x; b[1]=b0.y; b[2]=b0.z; b[3]=b0.w;
            if constexpr (RN == 8) {
                float4 b1v = *(const float4*)&Bs[kk][tx * 4 + 64];
                b[4]=b1v.x; b[5]=b1v.y; b[6]=b1v.z; b[7]=b1v.w;
            }
#pragma unroll
            for (int i = 0; i < 8; i++)
#pragma unroll
                for (int j = 0; j < RN; j++)
                    acc[i][j] = fmaf(a[i], b[j], acc[i][j]);
        }
        __syncthreads();
    }
    // epilogue
#pragma unroll
    for (int i = 0; i < 8; i++) {
        int r = row0 + ty * 4 + (i & 3) + (i >> 2) * 64;
        if (r >= N_NODES) continue;
#pragma unroll
        for (int jg = 0; jg < RN / 4; jg++) {
            float4 o;
            o.x = acc[i][jg * 4 + 0]; o.y = acc[i][jg * 4 + 1];
            o.z = acc[i][jg * 4 + 2]; o.w = acc[i][jg * 4 + 3];
            *(float4*)(Hout + (size_t)r * NOUT + tx * 4 + jg * 64) = o;
        }
    }
}

// ---------------- attention scores (a_s, a_d) ----------------
// Layer 1: warp per node, lane -> 4 channels of one head; reduce within groups of 4.
__global__ void scores1_kernel(const float* __restrict__ att_s,
                               const float* __restrict__ att_d)
{
    int t = blockIdx.x * blockDim.x + threadIdx.x;
    int n = t >> 5;
    if (n >= N_NODES) return;
    int l = t & 31;
    int head = l >> 2;
    float4 v  = *(const float4*)&g_h1[(size_t)n * HID + l * 4];
    float4 s4 = *(const float4*)&att_s[l * 4];
    float4 d4 = *(const float4*)&att_d[l * 4];
    float ps = v.x*s4.x + v.y*s4.y + v.z*s4.z + v.w*s4.w;
    float pd = v.x*d4.x + v.y*d4.y + v.z*d4.z + v.w*d4.w;
    ps += __shfl_xor_sync(0xffffffffu, ps, 1); ps += __shfl_xor_sync(0xffffffffu, ps, 2);
    pd += __shfl_xor_sync(0xffffffffu, pd, 1); pd += __shfl_xor_sync(0xffffffffu, pd, 2);
    if ((l & 3) == 0) {
        g_as1[n * HEADS1 + head] = ps;
        g_ad1[n * HEADS1 + head] = pd;
    }
}

// Layer 2: warp per node, lane -> 2 channels, full-warp reduce.
__global__ void scores2_kernel(const float* __restrict__ att_s,
                               const float* __restrict__ att_d)
{
    int t = blockIdx.x * blockDim.x + threadIdx.x;
    int n = t >> 5;
    if (n >= N_NODES) return;
    int l = t & 31;
    float2 v  = *(const float2*)&g_h2[(size_t)n * OUT_F + l * 2];
    float2 s2 = *(const float2*)&att_s[l * 2];
    float2 d2 = *(const float2*)&att_d[l * 2];
    float ps = v.x*s2.x + v.y*s2.y;
    float pd = v.x*d2.x + v.y*d2.y;
#pragma unroll
    for (int off = 16; off > 0; off >>= 1) {
        ps += __shfl_xor_sync(0xffffffffu, ps, off);
        pd += __shfl_xor_sync(0xffffffffu, pd, off);
    }
    if (l == 0) { g_as2[n] = ps; g_ad2[n] = pd; }
}

// ---------------- edge passes ----------------
// edge_index is int32 on device (JAX default x64-disabled downcasts int64 -> int32).
__device__ __forceinline__ void edge_sd(const int* __restrict__ ei, int e, int& s, int& d) {
    if (e < E0) { s = ei[e]; d = ei[E0 + e]; }
    else        { s = d = e - E0; }
}

template<int LAYER>
__global__ void edge_max_kernel(const int* __restrict__ ei) {
    constexpr int H = (LAYER == 1) ? HEADS1 : 1;
    const float* as = (LAYER == 1) ? g_as1 : g_as2;
    const float* ad = (LAYER == 1) ? g_ad1 : g_ad2;
    unsigned*    em = (LAYER == 1) ? g_emax1 : g_emax2;
    int idx = blockIdx.x * blockDim.x + threadIdx.x;
    if (idx >= ETOT * H) return;
    int e = idx / H, h = idx - e * H;
    int s, d; edge_sd(ei, e, s, d);
    float v = lrelu(as[s * H + h] + ad[d * H + h]);
    atomicMax(&em[d * H + h], fenc(v));
}

template<int LAYER>
__global__ void edge_sum_kernel(const int* __restrict__ ei) {
    constexpr int H = (LAYER == 1) ? HEADS1 : 1;
    const float*    as = (LAYER == 1) ? g_as1 : g_as2;
    const float*    ad = (LAYER == 1) ? g_ad1 : g_ad2;
    const unsigned* em = (LAYER == 1) ? g_emax1 : g_emax2;
    float*          dn = (LAYER == 1) ? g_den1 : g_den2;
    int idx = blockIdx.x * blockDim.x + threadIdx.x;
    if (idx >= ETOT * H) return;
    int e = idx / H, h = idx - e * H;
    int s, d; edge_sd(ei, e, s, d);
    float v = lrelu(as[s * H + h] + ad[d * H + h]);
    float w = __expf(v - fdec(em[d * H + h]));
    atomicAdd(&dn[d * H + h], w);
}

// warp per edge; lane covers TC/32 channels; vector red into out[dst].
template<int LAYER>
__global__ void edge_aggr_kernel(const int* __restrict__ ei) {
    constexpr int H  = (LAYER == 1) ? HEADS1 : 1;
    constexpr int TC = (LAYER == 1) ? HID : OUT_F;
    constexpr int V  = TC / 32;
    const float*    as   = (LAYER == 1) ? g_as1 : g_as2;
    const float*    ad   = (LAYER == 1) ? g_ad1 : g_ad2;
    const unsigned* em   = (LAYER == 1) ? g_emax1 : g_emax2;
    const float*    dn   = (LAYER == 1) ? g_den1 : g_den2;
    const float*    hsrc = (LAYER == 1) ? g_h1 : g_h2;
    float*          out  = (LAYER == 1) ? g_out1 : g_out2;

    int t = blockIdx.x * blockDim.x + threadIdx.x;
    int e = t >> 5;
    if (e >= ETOT) return;
    int l = t & 31;
    int s, d; edge_sd(ei, e, s, d);
    int head = (l * V) / (TC / H);
    float v = lrelu(as[s * H + head] + ad[d * H + head]);
    float alpha = __expf(v - fdec(em[d * H + head])) / (dn[d * H + head] + 1e-16f);

    if constexpr (V == 4) {
        float4 hv = *(const float4*)&hsrc[(size_t)s * TC + l * 4];
        float* p = &out[(size_t)d * TC + l * 4];
        asm volatile("red.global.add.v4.f32 [%0], {%1,%2,%3,%4};" ::
                     "l"(p), "f"(hv.x * alpha), "f"(hv.y * alpha),
                     "f"(hv.z * alpha), "f"(hv.w * alpha) : "memory");
    } else {
        float2 hv = *(const float2*)&hsrc[(size_t)s * TC + l * 2];
        float* p = &out[(size_t)d * TC + l * 2];
        asm volatile("red.global.add.v2.f32 [%0], {%1,%2};" ::
                     "l"(p), "f"(hv.x * alpha), "f"(hv.y * alpha) : "memory");
    }
}

// ---------------- bias2 + log_softmax ----------------
__global__ void lsm_kernel(const float* __restrict__ b2, float* __restrict__ y) {
    int t = blockIdx.x * blockDim.x + threadIdx.x;
    int n = t >> 5;
    if (n >= N_NODES) return;
    int l = t & 31;
    float v0 = g_out2[(size_t)n * OUT_F + l]      + b2[l];
    float v1 = g_out2[(size_t)n * OUT_F + 32 + l] + b2[32 + l];
    float m = fmaxf(v0, v1);
#pragma unroll
    for (int off = 16; off > 0; off >>= 1)
        m = fmaxf(m, __shfl_xor_sync(0xffffffffu, m, off));
    float ss = __expf(v0 - m) + __expf(v1 - m);
#pragma unroll
    for (int off = 16; off > 0; off >>= 1)
        ss += __shfl_xor_sync(0xffffffffu, ss, off);
    float lg = __logf(ss);
    y[(size_t)n * OUT_F + l]      = v0 - m - lg;
    y[(size_t)n * OUT_F + 32 + l] = v1 - m - lg;
}

// ---------------- launch ----------------
extern "C" void kernel_launch(void* const* d_in, const int* in_sizes, int n_in,
                              void* d_out, int out_size) {
    const float* x      = (const float*)d_in[0];
    const int*   ei     = (const int*)d_in[1];
    const float* W1     = (const float*)d_in[2];
    const float* att_s1 = (const float*)d_in[3];
    const float* att_d1 = (const float*)d_in[4];
    const float* b1     = (const float*)d_in[5];
    const float* W2     = (const float*)d_in[6];
    const float* att_s2 = (const float*)d_in[7];
    const float* att_d2 = (const float*)d_in[8];
    const float* b2     = (const float*)d_in[9];
    float*       y      = (float*)d_out;

    const int TB = 256;
    // init accumulators
    init_kernel<<<(N_NODES * HID / 4 + TB - 1) / TB, TB>>>();
    // layer 1
    gemm_kernel<IN_F, HID, false><<<(N_NODES + 127) / 128, 256>>>(x, W1, b1);
    scores1_kernel<<<(N_NODES * 32 + TB - 1) / TB, TB>>>(att_s1, att_d1);
    edge_max_kernel<1><<<(ETOT * HEADS1 + TB - 1) / TB, TB>>>(ei);
    edge_sum_kernel<1><<<(ETOT * HEADS1 + TB - 1) / TB, TB>>>(ei);
    edge_aggr_kernel<1><<<(ETOT * 32 + TB - 1) / TB, TB>>>(ei);
    // layer 2 (elu(out1+b1) fused into A-tile load)
    gemm_kernel<HID, OUT_F, true><<<(N_NODES + 127) / 128, 256>>>(x, W2, b1);
    scores2_kernel<<<(N_NODES * 32 + TB - 1) / TB, TB>>>(att_s2, att_d2);
    edge_max_kernel<2><<<(ETOT + TB - 1) / TB, TB>>>(ei);
    edge_sum_kernel<2><<<(ETOT + TB - 1) / TB, TB>>>(ei);
    edge_aggr_kernel<2><<<(ETOT * 32 + TB - 1) / TB, TB>>>(ei);
    // bias2 + log_softmax
    lsm_kernel<<<(N_NODES * 32 + TB - 1) / TB, TB>>>(b2, y);
}